// round 12
// baseline (speedup 1.0000x reference)
#include <cuda_runtime.h>

#define TSEQ 512
#define INF  14
#define HID  8

typedef unsigned long long ull;

__device__ __forceinline__ ull pk(float lo, float hi){
    ull r; asm("mov.b64 %0, {%1,%2};" : "=l"(r) : "f"(lo), "f"(hi)); return r;
}
__device__ __forceinline__ float2 upk(ull v){
    float2 r; asm("mov.b64 {%0,%1}, %2;" : "=f"(r.x), "=f"(r.y) : "l"(v)); return r;
}
__device__ __forceinline__ ull ffma2(ull a, ull b, ull c){
    ull d; asm("fma.rn.f32x2 %0, %1, %2, %3;" : "=l"(d) : "l"(a), "l"(b), "l"(c)); return d;
}
__device__ __forceinline__ float tanhx(float x){
    float r; asm("tanh.approx.f32 %0, %1;" : "=f"(r) : "f"(x)); return r;
}
// pre-scaled sigmoid: the gate's weights/bias were multiplied by 0.5,
// so sigmoid(orig) = 0.5*tanh(s) + 0.5
__device__ __forceinline__ float sig_ps(float s){
    return fmaf(0.5f, tanhx(s), 0.5f);
}

// 2 batch elements per warp, 16 lanes each: lane = eh*16 + p*8 + j.
// p=0 lanes are the element's LAYER-1 engine, p=1 lanes its LAYER-2 engine.
// Both halves execute ONE uniform instruction stream; only weight data differs:
//   early dot: acc = bias + Sum_{k<7} A[k]*x[k] + Sum_{k<4} B[k]*Q[k]
//     p=0: A=Wih1 pairs, B=Whh1 pairs, Q=h1(t-1) pairs
//     p=1: A=0,          B=Whh2 pairs, Q=h2(t-1) pairs
//   act block 1 -> commit h,c on p=0 only  => h1(t)
//   8 shfl: R[k] = h1(t) pairs (sources = p=0 half)
//   late dot:  acc += Sum_{k<4} C[k]*R[k]
//     p=0: C=0 ; p=1: C=Wih2 pairs
//   act block 2 -> commit h,c on p=1 only  => h2(t)
//   8 shfl: Q[k] = own-half h pairs (p=0 gets h1(t), p=1 gets h2(t)) for t+1.
// Depth-2 x prefetch keeps the LDG stream off the recurrence critical path.
__global__ __launch_bounds__(32, 14) void lstm_forex_kernel(
    const float* __restrict__ x,
    const float* __restrict__ Wih1, const float* __restrict__ Whh1,
    const float* __restrict__ bih1, const float* __restrict__ bhh1,
    const float* __restrict__ Wih2, const float* __restrict__ Whh2,
    const float* __restrict__ bih2, const float* __restrict__ bhh2,
    const float* __restrict__ bn_gamma, const float* __restrict__ bn_beta,
    const float* __restrict__ bn_mean, const float* __restrict__ bn_var,
    const float* __restrict__ w1, const float* __restrict__ b1,
    const float* __restrict__ w2, const float* __restrict__ b2,
    float* __restrict__ out, int Bn)
{
    const int lane  = threadIdx.x & 31;
    const int j     = lane & 7;
    const int p     = (lane >> 3) & 1;      // 0: layer-1 engine, 1: layer-2 engine
    const int ebase = lane & 16;            // element's base lane (p=0 half start)
    const int e     = blockIdx.x * 2 + (lane >> 4);
    const bool valid = (e < Bn);
    const int ec = valid ? e : (Bn > 0 ? Bn - 1 : 0);
    const unsigned FULL = 0xffffffffu;

    // gate scales: i,f,o pre-scaled by 0.5 (sigmoid via tanh), g unscaled
    const float gs[4] = {0.5f, 0.5f, 1.0f, 0.5f};

    // ---- uniform weight arrays, data differs by p ----
    ull A[4][7], Bw[4][4], Cw[4][4], pb[4];
    if (p == 0){
#pragma unroll
        for (int g = 0; g < 4; g++){
            const int row = g * 8 + j;
            const float s = gs[g];
#pragma unroll
            for (int k = 0; k < 7; k++)
                A[g][k] = pk(s * Wih1[row*14 + 2*k], s * Wih1[row*14 + 2*k + 1]);
#pragma unroll
            for (int k = 0; k < 4; k++){
                Bw[g][k] = pk(s * Whh1[row*8 + 2*k], s * Whh1[row*8 + 2*k + 1]);
                Cw[g][k] = 0ull;
            }
            pb[g] = pk(s * (bih1[row] + bhh1[row]), 0.f);
        }
    } else {
#pragma unroll
        for (int g = 0; g < 4; g++){
            const int row = g * 8 + j;
            const float s = gs[g];
#pragma unroll
            for (int k = 0; k < 7; k++) A[g][k] = 0ull;
#pragma unroll
            for (int k = 0; k < 4; k++){
                Bw[g][k] = pk(s * Whh2[row*8 + 2*k], s * Whh2[row*8 + 2*k + 1]);
                Cw[g][k] = pk(s * Wih2[row*8 + 2*k], s * Wih2[row*8 + 2*k + 1]);
            }
            pb[g] = pk(s * (bih2[row] + bhh2[row]), 0.f);
        }
    }

    // x[e, t, :]: 14 floats = 7 packed pairs; depth-2 double buffer.
    // Both halves load the same element's x (harmless for p=1; A=0 there).
    const ull* px = reinterpret_cast<const ull*>(x) + (size_t)ec * (TSEQ * INF / 2);
    ull xb[2][7];
#pragma unroll
    for (int k = 0; k < 7; k++) xb[0][k] = px[k];        // x(0)
#pragma unroll
    for (int k = 0; k < 7; k++) xb[1][k] = px[7 + k];    // x(1)
    px += 14;                                            // -> x(2)

    // Q: own-layer previous-h pairs; starts at 0 (h1(-1)=h2(-1)=0)
    ull Q[4] = {0ull,0ull,0ull,0ull};
    float h = 0.f, c = 0.f;                 // my layer's state
    const float pf = (float)p;              // 0.0 on layer-1 lanes, 1.0 on layer-2

#pragma unroll 2
    for (int t = 0; t < TSEQ; t++){
        ull* cur = xb[t & 1];

        // ---- early dot ----
        ull a0 = pb[0], a1 = pb[1], a2 = pb[2], a3 = pb[3];
#pragma unroll
        for (int k = 0; k < 7; k++){
            a0 = ffma2(A[0][k], cur[k], a0);
            a1 = ffma2(A[1][k], cur[k], a1);
            a2 = ffma2(A[2][k], cur[k], a2);
            a3 = ffma2(A[3][k], cur[k], a3);
        }
        // cur free: prefetch x(t+2) (~2 steps of cover)
        if (t + 2 < TSEQ){
#pragma unroll
            for (int k = 0; k < 7; k++) cur[k] = px[k];
            px += 7;
        }
#pragma unroll
        for (int k = 0; k < 4; k++){
            a0 = ffma2(Bw[0][k], Q[k], a0);
            a1 = ffma2(Bw[1][k], Q[k], a1);
            a2 = ffma2(Bw[2][k], Q[k], a2);
            a3 = ffma2(Bw[3][k], Q[k], a3);
        }
        // ---- act block 1: commit on p=0 (layer 1) -> h1(t) ----
        {
            const float2 u0 = upk(a0), u1 = upk(a1), u2 = upk(a2), u3 = upk(a3);
            const float ai = sig_ps(u0.x + u0.y);
            const float af = sig_ps(u1.x + u1.y);
            const float ag = tanhx(u2.x + u2.y);
            const float ao = sig_ps(u3.x + u3.y);
            const float cn = fmaf(af, c, ai * ag);
            const float hn = ao * tanhx(cn);
            // commit only on p==0 (branchless select; p=1 keeps old state)
            c = fmaf(pf, c - cn, cn);   // p?c:cn
            h = fmaf(pf, h - hn, hn);
        }
        // ---- 8 shfl: h1(t) pairs from the p=0 half -> R ----
        ull R[4];
#pragma unroll
        for (int k = 0; k < 4; k++){
            const float ha = __shfl_sync(FULL, h, ebase + 2*k);
            const float hb = __shfl_sync(FULL, h, ebase + 2*k + 1);
            R[k] = pk(ha, hb);
        }
        // ---- late dot: += C·R (zero on p=0) ----
#pragma unroll
        for (int k = 0; k < 4; k++){
            a0 = ffma2(Cw[0][k], R[k], a0);
            a1 = ffma2(Cw[1][k], R[k], a1);
            a2 = ffma2(Cw[2][k], R[k], a2);
            a3 = ffma2(Cw[3][k], R[k], a3);
        }
        // ---- act block 2: commit on p=1 (layer 2) -> h2(t) ----
        {
            const float2 u0 = upk(a0), u1 = upk(a1), u2 = upk(a2), u3 = upk(a3);
            const float ai = sig_ps(u0.x + u0.y);
            const float af = sig_ps(u1.x + u1.y);
            const float ag = tanhx(u2.x + u2.y);
            const float ao = sig_ps(u3.x + u3.y);
            const float cn = fmaf(af, c, ai * ag);
            const float hn = ao * tanhx(cn);
            // commit only on p==1
            c = fmaf(pf, cn - c, c);    // p?cn:c
            h = fmaf(pf, hn - h, h);
        }
        // ---- 8 shfl: own-half h pairs -> Q for t+1 ----
        const int ob = ebase + 8*p;
#pragma unroll
        for (int k = 0; k < 4; k++){
            const float ha = __shfl_sync(FULL, h, ob + 2*k);
            const float hb = __shfl_sync(FULL, h, ob + 2*k + 1);
            Q[k] = pk(ha, hb);
        }
    }

    // ---------------- epilogue: BatchNorm (eval) + MLP head ----------------
    // h on p=1 lanes = h2(T-1); compute uniformly, reduce within 8-lane group,
    // write from the p=1, j=0 lane of each element.
    const float scale = bn_gamma[j] * rsqrtf(bn_var[j] + 1e-5f);
    const float nrm   = fmaf(h - bn_mean[j], scale, bn_beta[j]);

    float p0 = w1[0 * 8 + j] * nrm;
    float p1 = w1[1 * 8 + j] * nrm;
    float p2 = w1[2 * 8 + j] * nrm;
    float p3 = w1[3 * 8 + j] * nrm;
#pragma unroll
    for (int off = 4; off > 0; off >>= 1){   // stays within aligned 8-lane groups
        p0 += __shfl_xor_sync(FULL, p0, off);
        p1 += __shfl_xor_sync(FULL, p1, off);
        p2 += __shfl_xor_sync(FULL, p2, off);
        p3 += __shfl_xor_sync(FULL, p3, off);
    }
    if (valid && p == 1 && j == 0){
        float o = b2[0];
        o = fmaf(w2[0], fmaxf(p0 + b1[0], 0.f), o);
        o = fmaf(w2[1], fmaxf(p1 + b1[1], 0.f), o);
        o = fmaf(w2[2], fmaxf(p2 + b1[2], 0.f), o);
        o = fmaf(w2[3], fmaxf(p3 + b1[3], 0.f), o);
        out[e] = o;
    }
}

extern "C" void kernel_launch(void* const* d_in, const int* in_sizes, int n_in,
                              void* d_out, int out_size)
{
    const float* x        = (const float*)d_in[0];
    const float* Wih1     = (const float*)d_in[1];
    const float* Whh1     = (const float*)d_in[2];
    const float* bih1     = (const float*)d_in[3];
    const float* bhh1     = (const float*)d_in[4];
    const float* Wih2     = (const float*)d_in[5];
    const float* Whh2     = (const float*)d_in[6];
    const float* bih2     = (const float*)d_in[7];
    const float* bhh2     = (const float*)d_in[8];
    const float* bn_gamma = (const float*)d_in[9];
    const float* bn_beta  = (const float*)d_in[10];
    const float* bn_mean  = (const float*)d_in[11];
    const float* bn_var   = (const float*)d_in[12];
    const float* w1       = (const float*)d_in[13];
    const float* b1       = (const float*)d_in[14];
    const float* w2       = (const float*)d_in[15];
    const float* b2       = (const float*)d_in[16];

    const int Bn = in_sizes[0] / (TSEQ * INF);
    const int grid = (Bn + 1) / 2;            // 2 batch elements per warp

    lstm_forex_kernel<<<grid, 32>>>(x, Wih1, Whh1, bih1, bhh1,
                                    Wih2, Whh2, bih2, bhh2,
                                    bn_gamma, bn_beta, bn_mean, bn_var,
                                    w1, b1, w2, b2,
                                    (float*)d_out, Bn);
}

// round 13
// speedup vs baseline: 2.9060x; 2.9060x over previous
#include <cuda_runtime.h>

#define TSEQ 512
#define INF  14

typedef unsigned long long ull;

__device__ __forceinline__ ull pk(float lo, float hi){
    ull r; asm("mov.b64 %0, {%1,%2};" : "=l"(r) : "f"(lo), "f"(hi)); return r;
}
__device__ __forceinline__ float2 upk(ull v){
    float2 r; asm("mov.b64 {%0,%1}, %2;" : "=f"(r.x), "=f"(r.y) : "l"(v)); return r;
}
__device__ __forceinline__ ull ffma2(ull a, ull b, ull c){
    ull d; asm("fma.rn.f32x2 %0, %1, %2, %3;" : "=l"(d) : "l"(a), "l"(b), "l"(c)); return d;
}
__device__ __forceinline__ float tanhx(float x){
    float r; asm("tanh.approx.f32 %0, %1;" : "=f"(r) : "f"(x)); return r;
}
// gate weights pre-scaled by 0.5 => sigmoid(orig) = 0.5*tanh(s)+0.5
__device__ __forceinline__ float sig_ps(float s){
    return fmaf(0.5f, tanhx(s), 0.5f);
}
__device__ __forceinline__ void cpa8(void* smem_dst, const void* gsrc){
    unsigned sa = (unsigned)__cvta_generic_to_shared(smem_dst);
    asm volatile("cp.async.ca.shared.global [%0], [%1], 8;" :: "r"(sa), "l"(gsrc));
}
#define CP_COMMIT() asm volatile("cp.async.commit_group;" ::: "memory")
#define CP_WAIT1()  asm volatile("cp.async.wait_group 1;"  ::: "memory")

// 2 batch elements per warp, 16 lanes each: lane = eh*16 + p*8 + j.
// p=0 lanes: LAYER-1 engine (h-index j); p=1 lanes: LAYER-2 engine.
// SKEWED pipeline: at iter i, p=0 commits h1(i), p=1 commits h2(i-1).
// One uniform instruction stream; per-lane weight DATA differs:
//   acc = pb + Sum_{k<4} B[k]*Qh1[k] + Sum_{k<4} W2[k]*X[k] + Sum_{k=4..6} W2[k]*lds[k]
//   p=0: B=Whh1, W2=Wih1(7 pairs), X=x pairs (from smem)
//   p=1: B=Wih2, W2[0..3]=Whh2, W2[4..6]=0, X=Qh2 (h2(i-2) pairs)
// ONE act block per iter commits both layers (skew) -> 5 MUFU/step, no selects.
// x staged via cp.async depth-2 into smem (no register double-buffer).
__global__ __launch_bounds__(32, 14) void lstm_forex_kernel(
    const float* __restrict__ x,
    const float* __restrict__ Wih1, const float* __restrict__ Whh1,
    const float* __restrict__ bih1, const float* __restrict__ bhh1,
    const float* __restrict__ Wih2, const float* __restrict__ Whh2,
    const float* __restrict__ bih2, const float* __restrict__ bhh2,
    const float* __restrict__ bn_gamma, const float* __restrict__ bn_beta,
    const float* __restrict__ bn_mean, const float* __restrict__ bn_var,
    const float* __restrict__ w1, const float* __restrict__ b1,
    const float* __restrict__ w2, const float* __restrict__ b2,
    float* __restrict__ out, int Bn)
{
    __shared__ __align__(16) ull sx[2][2][8];   // [elem][buf][pair]

    const int lane  = threadIdx.x & 31;
    const int j     = lane & 7;
    const int p     = (lane >> 3) & 1;
    const int eh    = lane >> 4;
    const int ebase = lane & 16;
    const int e     = blockIdx.x * 2 + eh;
    const bool valid = (e < Bn);
    const int ec = valid ? e : (Bn > 0 ? Bn - 1 : 0);
    const bool isP1 = (p == 1);
    const unsigned FULL = 0xffffffffu;

    // ---- per-lane weights (union layout, constant indices only) ----
    ull W2[4][7], B[4][4], pb[4];
#pragma unroll
    for (int g = 0; g < 4; g++){
        const int row = g * 8 + j;
        const float s = (g == 2) ? 1.0f : 0.5f;   // i,f,o pre-scaled
        if (!isP1){
#pragma unroll
            for (int k = 0; k < 7; k++)
                W2[g][k] = pk(s * Wih1[row*14 + 2*k], s * Wih1[row*14 + 2*k + 1]);
#pragma unroll
            for (int k = 0; k < 4; k++)
                B[g][k] = pk(s * Whh1[row*8 + 2*k], s * Whh1[row*8 + 2*k + 1]);
            pb[g] = pk(s * (bih1[row] + bhh1[row]), 0.f);
        } else {
#pragma unroll
            for (int k = 0; k < 4; k++)
                W2[g][k] = pk(s * Whh2[row*8 + 2*k], s * Whh2[row*8 + 2*k + 1]);
#pragma unroll
            for (int k = 4; k < 7; k++) W2[g][k] = 0ull;
#pragma unroll
            for (int k = 0; k < 4; k++)
                B[g][k] = pk(s * Wih2[row*8 + 2*k], s * Wih2[row*8 + 2*k + 1]);
            pb[g] = pk(s * (bih2[row] + bhh2[row]), 0.f);
        }
    }

    // x byte base for my element; x(t) pair k at +t*56 + k*8
    const char* gx = (const char*)x + (size_t)ec * (TSEQ * INF * 4);

    // prime smem: x(0) -> buf0, x(1) -> buf1 (one commit group each)
    if (p == 0 && j < 7) cpa8(&sx[eh][0][j], gx + j*8);
    CP_COMMIT();
    if (p == 0 && j < 7) cpa8(&sx[eh][1][j], gx + 56 + j*8);
    CP_COMMIT();
    CP_WAIT1();            // x(0) complete (<=1 pending)
    __syncwarp(FULL);

    ull Qh1[4] = {0,0,0,0}, Qh2[4] = {0,0,0,0}, X[4];
    float h = 0.f, c = 0.f;

    // ================= peel i=0: p=0 -> h1(0); p=1 stays 0 =================
    {
        ull t0 = sx[eh][0][0], t1 = sx[eh][0][1], t2 = sx[eh][0][2],
            t3 = sx[eh][0][3], t4 = sx[eh][0][4], t5 = sx[eh][0][5], t6 = sx[eh][0][6];
        X[0] = isP1 ? 0ull : t0;  X[1] = isP1 ? 0ull : t1;
        X[2] = isP1 ? 0ull : t2;  X[3] = isP1 ? 0ull : t3;
        ull a0 = pb[0], a1 = pb[1], a2 = pb[2], a3 = pb[3];
#pragma unroll
        for (int k = 0; k < 4; k++){
            a0 = ffma2(W2[0][k], X[k], a0); a1 = ffma2(W2[1][k], X[k], a1);
            a2 = ffma2(W2[2][k], X[k], a2); a3 = ffma2(W2[3][k], X[k], a3);
        }
        a0 = ffma2(W2[0][4], t4, a0); a1 = ffma2(W2[1][4], t4, a1);
        a2 = ffma2(W2[2][4], t4, a2); a3 = ffma2(W2[3][4], t4, a3);
        a0 = ffma2(W2[0][5], t5, a0); a1 = ffma2(W2[1][5], t5, a1);
        a2 = ffma2(W2[2][5], t5, a2); a3 = ffma2(W2[3][5], t5, a3);
        a0 = ffma2(W2[0][6], t6, a0); a1 = ffma2(W2[1][6], t6, a1);
        a2 = ffma2(W2[2][6], t6, a2); a3 = ffma2(W2[3][6], t6, a3);
        const float2 u0 = upk(a0), u1 = upk(a1), u2 = upk(a2), u3 = upk(a3);
        const float ai = sig_ps(u0.x + u0.y);
        const float af = sig_ps(u1.x + u1.y);
        const float ag = tanhx(u2.x + u2.y);
        const float ao = sig_ps(u3.x + u3.y);
        const float cn = fmaf(af, 0.f, ai * ag);
        const float hn = ao * tanhx(cn);
        h = isP1 ? 0.f : hn;
        c = isP1 ? 0.f : cn;
#pragma unroll
        for (int k = 0; k < 4; k++){
            Qh1[k] = pk(__shfl_sync(FULL, h, ebase + 2*k),
                        __shfl_sync(FULL, h, ebase + 2*k + 1));
            Qh2[k] = 0ull;    // h2(-1) = 0 (p=1 h is 0 anyway)
        }
        if (p == 0 && j < 7) cpa8(&sx[eh][0][j], gx + 2*56 + j*8);  // x(2)
        CP_COMMIT();
        CP_WAIT1();          // x(1) complete
        __syncwarp(FULL);
    }

    // ================= main loop: i = 1..512 (256 x 2 steps) =================
#define STEP(IVAL, BUFIDX)                                                      \
    {                                                                           \
        ull t0 = sx[eh][BUFIDX][0], t1 = sx[eh][BUFIDX][1],                     \
            t2 = sx[eh][BUFIDX][2], t3 = sx[eh][BUFIDX][3],                     \
            t4 = sx[eh][BUFIDX][4], t5 = sx[eh][BUFIDX][5],                     \
            t6 = sx[eh][BUFIDX][6];                                             \
        X[0] = isP1 ? Qh2[0] : t0;  X[1] = isP1 ? Qh2[1] : t1;                  \
        X[2] = isP1 ? Qh2[2] : t2;  X[3] = isP1 ? Qh2[3] : t3;                  \
        ull a0 = pb[0], a1 = pb[1], a2 = pb[2], a3 = pb[3];                     \
        _Pragma("unroll")                                                       \
        for (int k = 0; k < 4; k++){                                            \
            a0 = ffma2(B[0][k], Qh1[k], a0); a1 = ffma2(B[1][k], Qh1[k], a1);   \
            a2 = ffma2(B[2][k], Qh1[k], a2); a3 = ffma2(B[3][k], Qh1[k], a3);   \
        }                                                                       \
        _Pragma("unroll")                                                       \
        for (int k = 0; k < 4; k++){                                            \
            a0 = ffma2(W2[0][k], X[k], a0); a1 = ffma2(W2[1][k], X[k], a1);     \
            a2 = ffma2(W2[2][k], X[k], a2); a3 = ffma2(W2[3][k], X[k], a3);     \
        }                                                                       \
        a0 = ffma2(W2[0][4], t4, a0); a1 = ffma2(W2[1][4], t4, a1);             \
        a2 = ffma2(W2[2][4], t4, a2); a3 = ffma2(W2[3][4], t4, a3);             \
        a0 = ffma2(W2[0][5], t5, a0); a1 = ffma2(W2[1][5], t5, a1);             \
        a2 = ffma2(W2[2][5], t5, a2); a3 = ffma2(W2[3][5], t5, a3);             \
        a0 = ffma2(W2[0][6], t6, a0); a1 = ffma2(W2[1][6], t6, a1);             \
        a2 = ffma2(W2[2][6], t6, a2); a3 = ffma2(W2[3][6], t6, a3);             \
        if ((IVAL) <= 509 && p == 0 && j < 7)                                   \
            cpa8(&sx[eh][BUFIDX][j], gx + (size_t)((IVAL) + 2)*56 + j*8);       \
        CP_COMMIT();                                                            \
        const float2 u0 = upk(a0), u1 = upk(a1), u2 = upk(a2), u3 = upk(a3);    \
        const float ai = sig_ps(u0.x + u0.y);                                   \
        const float af = sig_ps(u1.x + u1.y);                                   \
        const float ag = tanhx(u2.x + u2.y);                                    \
        const float ao = sig_ps(u3.x + u3.y);                                   \
        const float cn = fmaf(af, c, ai * ag);                                  \
        const float hn = ao * tanhx(cn);                                        \
        h = hn; c = cn;                                                         \
        _Pragma("unroll")                                                       \
        for (int k = 0; k < 4; k++){                                            \
            Qh1[k] = pk(__shfl_sync(FULL, h, ebase + 2*k),                      \
                        __shfl_sync(FULL, h, ebase + 2*k + 1));                 \
            Qh2[k] = pk(__shfl_sync(FULL, h, ebase + 8 + 2*k),                  \
                        __shfl_sync(FULL, h, ebase + 8 + 2*k + 1));             \
        }                                                                       \
        CP_WAIT1();                                                             \
        __syncwarp(FULL);                                                       \
    }

#pragma unroll 1
    for (int ii = 0; ii < 256; ii++){
        const int i1 = 2*ii + 1;
        STEP(i1,     1);     // odd i  -> buf1
        STEP(i1 + 1, 0);     // even i -> buf0
    }
#undef STEP

    // h on p=1 lanes = h2(511)
    // ---------------- epilogue: BatchNorm (eval) + MLP head ----------------
    const float scale = bn_gamma[j] * rsqrtf(bn_var[j] + 1e-5f);
    const float nrm   = fmaf(h - bn_mean[j], scale, bn_beta[j]);

    float p0 = w1[0 * 8 + j] * nrm;
    float p1 = w1[1 * 8 + j] * nrm;
    float p2 = w1[2 * 8 + j] * nrm;
    float p3 = w1[3 * 8 + j] * nrm;
#pragma unroll
    for (int off = 4; off > 0; off >>= 1){   // stays within aligned 8-lane groups
        p0 += __shfl_xor_sync(FULL, p0, off);
        p1 += __shfl_xor_sync(FULL, p1, off);
        p2 += __shfl_xor_sync(FULL, p2, off);
        p3 += __shfl_xor_sync(FULL, p3, off);
    }
    if (valid && isP1 && j == 0){
        float o = b2[0];
        o = fmaf(w2[0], fmaxf(p0 + b1[0], 0.f), o);
        o = fmaf(w2[1], fmaxf(p1 + b1[1], 0.f), o);
        o = fmaf(w2[2], fmaxf(p2 + b1[2], 0.f), o);
        o = fmaf(w2[3], fmaxf(p3 + b1[3], 0.f), o);
        out[e] = o;
    }
}

extern "C" void kernel_launch(void* const* d_in, const int* in_sizes, int n_in,
                              void* d_out, int out_size)
{
    const float* x        = (const float*)d_in[0];
    const float* Wih1     = (const float*)d_in[1];
    const float* Whh1     = (const float*)d_in[2];
    const float* bih1     = (const float*)d_in[3];
    const float* bhh1     = (const float*)d_in[4];
    const float* Wih2     = (const float*)d_in[5];
    const float* Whh2     = (const float*)d_in[6];
    const float* bih2     = (const float*)d_in[7];
    const float* bhh2     = (const float*)d_in[8];
    const float* bn_gamma = (const float*)d_in[9];
    const float* bn_beta  = (const float*)d_in[10];
    const float* bn_mean  = (const float*)d_in[11];
    const float* bn_var   = (const float*)d_in[12];
    const float* w1       = (const float*)d_in[13];
    const float* b1       = (const float*)d_in[14];
    const float* w2       = (const float*)d_in[15];
    const float* b2       = (const float*)d_in[16];

    const int Bn = in_sizes[0] / (TSEQ * INF);
    const int grid = (Bn + 1) / 2;            // 2 batch elements per warp

    lstm_forex_kernel<<<grid, 32>>>(x, Wih1, Whh1, bih1, bhh1,
                                    Wih2, Whh2, bih2, bhh2,
                                    bn_gamma, bn_beta, bn_mean, bn_var,
                                    w1, b1, w2, b2,
                                    (float*)d_out, Bn);
}